// round 1
// baseline (speedup 1.0000x reference)
#include <cuda_runtime.h>
#include <math.h>

#define NG 8
#define NT 2048
#define NH 2048
#define NE 8
#define CAP 320
#define NTOK (NG * NT)          // 16384
#define TPB 64                  // tokens per block (kernel 1)
#define SEGS 8                  // H segments per token
#define SEGF (NH / SEGS)        // 256 floats per segment
#define THREADS1 512

// scratch: argmax expert id per token (between kernel 1 and kernel 2)
__device__ unsigned char g_expert_id[NTOK];

__device__ __forceinline__ void fma2(unsigned long long& acc,
                                     unsigned long long a,
                                     unsigned long long b) {
    asm volatile("fma.rn.f32x2 %0, %1, %2, %0;" : "+l"(acc) : "l"(a), "l"(b));
}

// ---------------------------------------------------------------------------
// Kernel 1: router logits + softmax stats + one-hot (pre-capacity) + argmax id
// Block: 64 tokens x full H. Warp w handles segment (w&7) for 32 tokens.
// All lanes of a warp process the SAME h -> W reads are smem broadcasts.
// ---------------------------------------------------------------------------
__global__ __launch_bounds__(THREADS1, 2)
void router_kernel(const float* __restrict__ hs,
                   const float* __restrict__ W,
                   const float* __restrict__ bias,
                   float* __restrict__ out) {
    extern __shared__ float sh[];
    float* sh_w     = sh;                    // 16384 floats: W packed [h2][e] pairs
    float* part     = sh + NE * NH;          // 64*65 floats (padded partials)
    float* sh_logit = part + TPB * 65;       // 64*9 floats
    int*   sh_arg   = (int*)(sh_logit + TPB * 9);   // 64
    float* sh_pmax  = (float*)(sh_arg + TPB);       // 64

    const int tid = threadIdx.x;

    // Load W into smem packed as consecutive (W[e][2k], W[e][2k+1]) pairs:
    // layout sh_w[h2*16 + e*2 + (h&1)]  ->  as u64: wp[h2*8 + e]
    for (int idx = tid; idx < NE * NH; idx += THREADS1) {
        int e = idx >> 11;
        int h = idx & (NH - 1);
        sh_w[((h >> 1) << 4) + (e << 1) + (h & 1)] = W[idx];
    }
    __syncthreads();

    const int warp = tid >> 5;
    const int lane = tid & 31;
    const int seg  = warp & 7;
    const int tl   = ((warp >> 3) << 5) | lane;   // 0..63 local token
    const int token = blockIdx.x * TPB + tl;

    const float4* xp =
        (const float4*)(hs + (size_t)token * NH + seg * SEGF);
    const unsigned long long* wrow =
        (const unsigned long long*)sh_w + (size_t)(seg * (SEGF / 2)) * 8;

    unsigned long long acc[NE];
#pragma unroll
    for (int e = 0; e < NE; e++) acc[e] = 0ULL;

#pragma unroll 4
    for (int i = 0; i < SEGF / 4; i++) {       // 64 iters of float4
        float4 x = xp[i];
        unsigned long long x01, x23;
        asm("mov.b64 %0, {%1, %2};" : "=l"(x01) : "f"(x.x), "f"(x.y));
        asm("mov.b64 %0, {%1, %2};" : "=l"(x23) : "f"(x.z), "f"(x.w));
        const unsigned long long* w0 = wrow + i * 16;
#pragma unroll
        for (int e = 0; e < NE; e++) fma2(acc[e], x01, w0[e]);
#pragma unroll
        for (int e = 0; e < NE; e++) fma2(acc[e], x23, w0[8 + e]);
    }

    // fold packed pairs, stash per-segment partials (pad 65 -> conflict-free)
#pragma unroll
    for (int e = 0; e < NE; e++) {
        float lo, hi;
        asm("mov.b64 {%0, %1}, %2;" : "=f"(lo), "=f"(hi) : "l"(acc[e]));
        part[tl * 65 + seg * 8 + e] = lo + hi;
    }
    __syncthreads();

    // reduce 8 segments per (token, expert); 512 threads cover 64x8
    {
        int rtl = tid >> 3, e = tid & 7;
        float s = 0.f;
#pragma unroll
        for (int sg = 0; sg < SEGS; sg++) s += part[rtl * 65 + sg * 8 + e];
        sh_logit[rtl * 9 + e] = s + bias[e];
    }
    __syncthreads();

    // per-token softmax stats (first-max argmax to match jnp.argmax)
    if (tid < TPB) {
        const float* l = sh_logit + tid * 9;
        float best = l[0];
        int bi = 0;
#pragma unroll
        for (int e = 1; e < NE; e++) {
            float v = l[e];
            if (v > best) { best = v; bi = e; }
        }
        float s = 0.f;
#pragma unroll
        for (int e = 0; e < NE; e++) s += expf(l[e] - best);
        sh_arg[tid]  = bi;
        sh_pmax[tid] = 1.0f / s;   // max prob = exp(0)/sum
    }
    __syncthreads();

    // write expert one-hot (capacity applied later) and logits
    {
        int rtl = tid >> 3, e = tid & 7;
        int gt = blockIdx.x * TPB + rtl;
        int bi = sh_arg[rtl];
        out[(size_t)gt * NE + e] = (e == bi) ? 1.0f : 0.0f;
        out[(size_t)NTOK * NE + NTOK + (size_t)gt * NE + e] =
            sh_logit[rtl * 9 + e];
    }
    if (tid < TPB) {
        int gt = blockIdx.x * TPB + tid;
        out[(size_t)NTOK * NE + gt] = sh_pmax[tid];
        g_expert_id[gt] = (unsigned char)sh_arg[tid];
    }
}

// ---------------------------------------------------------------------------
// Kernel 2: per-group inclusive cumsum of one-hot assignments; zero the
// one-hot entries whose priority exceeds EXPERT_CAPACITY. 8 blocks x 256 thr,
// 8 tokens/thread, two-level vector scan (shfl within warp, smem across).
// ---------------------------------------------------------------------------
__global__ void capacity_kernel(float* __restrict__ out) {
    const int g   = blockIdx.x;
    const int tid = threadIdx.x;          // 256
    const int lane = tid & 31, wrp = tid >> 5;

    unsigned long long ids =
        ((const unsigned long long*)g_expert_id)[g * (NT / 8) + tid];

    int c[NE];
#pragma unroll
    for (int e = 0; e < NE; e++) c[e] = 0;
#pragma unroll
    for (int i = 0; i < 8; i++) {
        int e = (int)((ids >> (8 * i)) & 0xFFULL);
#pragma unroll
        for (int ee = 0; ee < NE; ee++) c[ee] += (e == ee);
    }

    int s[NE];
#pragma unroll
    for (int e = 0; e < NE; e++) s[e] = c[e];
#pragma unroll
    for (int off = 1; off < 32; off <<= 1) {
#pragma unroll
        for (int e = 0; e < NE; e++) {
            int v = __shfl_up_sync(0xffffffffu, s[e], off);
            if (lane >= off) s[e] += v;
        }
    }

    __shared__ int wt[8][NE];
    if (lane == 31) {
#pragma unroll
        for (int e = 0; e < NE; e++) wt[wrp][e] = s[e];
    }
    __syncthreads();
    if (tid < NE) {            // exclusive scan of warp totals per expert
        int run = 0;
#pragma unroll
        for (int w = 0; w < 8; w++) {
            int v = wt[w][tid];
            wt[w][tid] = run;
            run += v;
        }
    }
    __syncthreads();

    int base[NE];
#pragma unroll
    for (int e = 0; e < NE; e++) base[e] = (s[e] - c[e]) + wt[wrp][e];

    int run2[NE];
#pragma unroll
    for (int e = 0; e < NE; e++) run2[e] = 0;

    const size_t tok0 = (size_t)g * NT + (size_t)tid * 8;
#pragma unroll
    for (int i = 0; i < 8; i++) {
        int e = (int)((ids >> (8 * i)) & 0xFFULL);
#pragma unroll
        for (int ee = 0; ee < NE; ee++) {
            int inc = (e == ee);
            run2[ee] += inc;
            if (inc && (base[ee] + run2[ee] > CAP))
                out[(tok0 + i) * NE + ee] = 0.0f;
        }
    }
}

// ---------------------------------------------------------------------------
extern "C" void kernel_launch(void* const* d_in, const int* in_sizes, int n_in,
                              void* d_out, int out_size) {
    const float* hs = (const float*)d_in[0];   // [8, 2048, 2048] f32
    const float* W  = (const float*)d_in[1];   // [8, 2048] f32
    const float* b  = (const float*)d_in[2];   // [8] f32
    float* out = (float*)d_out;

    const int smem =
        (NE * NH + TPB * 65 + TPB * 9) * 4 + TPB * 4 + TPB * 4;  // ~85 KB
    cudaFuncSetAttribute(router_kernel,
                         cudaFuncAttributeMaxDynamicSharedMemorySize, smem);

    router_kernel<<<NTOK / TPB, THREADS1, smem>>>(hs, W, b, out);
    capacity_kernel<<<NG, NT / 8>>>(out);
}

// round 2
// speedup vs baseline: 1.4851x; 1.4851x over previous
#include <cuda_runtime.h>
#include <math.h>

typedef unsigned long long u64;

#define NG 8
#define NT 2048
#define NH 2048
#define NE 8
#define CAP 320
#define NTOK (NG * NT)        // 16384
#define TPW 4                 // tokens per warp
#define WPB 8                 // warps per block
#define TPBK (TPW * WPB)      // 32 tokens per block
#define THREADS 256
#define NITER 16              // H chunks of 128 floats

// scratch: argmax expert id per token (kernel1 -> kernel2)
__device__ unsigned char g_expert_id[NTOK];

__device__ __forceinline__ void fma2(u64& acc, u64 a, u64 b) {
    asm("fma.rn.f32x2 %0, %1, %2, %0;" : "+l"(acc) : "l"(a), "l"(b));
}
__device__ __forceinline__ u64 add2(u64 a, u64 b) {
    u64 r; asm("add.rn.f32x2 %0, %1, %2;" : "=l"(r) : "l"(a), "l"(b));
    return r;
}
__device__ __forceinline__ u64 pack2(float lo, float hi) {
    u64 r; asm("mov.b64 %0, {%1, %2};" : "=l"(r) : "f"(lo), "f"(hi));
    return r;
}
__device__ __forceinline__ float fold2(u64 v) {
    float a, b; asm("mov.b64 {%0, %1}, %2;" : "=f"(a), "=f"(b) : "l"(v));
    return a + b;
}

// ---------------------------------------------------------------------------
// Kernel 1: warp = 4 tokens, lanes span H (coalesced LDG.128, nL=4).
// W in smem, lane-transposed u64 pairs -> conflict-free LDS.64 in mainloop.
// ---------------------------------------------------------------------------
__global__ __launch_bounds__(THREADS, 2)
void router_kernel(const float4* __restrict__ hs4,
                   const float* __restrict__ W,
                   const float* __restrict__ bias,
                   float* __restrict__ out) {
    extern __shared__ char smem[];
    u64*   shw      = (u64*)smem;                       // 8192 u64 = 64 KB
    float* sh_logit = (float*)(shw + NE * NH / 2);      // 32*9
    float* sh_bias  = sh_logit + TPBK * 9;              // 8
    int*   sh_arg   = (int*)(sh_bias + 8);              // 32

    const int tid  = threadIdx.x;
    const int lane = tid & 31, warp = tid >> 5;

    // Load W permuted: slot[(i*16 + e*2 + d)*32 + l] = (W[e][h], W[e][h+1])
    // where h = 2*(i*64 + 2l + d).  Lane l, iter i then reads its 16 u64
    // at consecutive-lane addresses (conflict-free LDS.64).
    const float2* W2 = (const float2*)W;
    for (int u = tid; u < NE * NH / 2; u += THREADS) {
        int e = u >> 10, h2 = u & 1023;
        int i = h2 >> 6, r = h2 & 63, l = r >> 1, d = r & 1;
        float2 w = W2[u];
        shw[((i * 16 + e * 2 + d) << 5) + l] = pack2(w.x, w.y);
    }
    if (tid < 8) sh_bias[tid] = bias[tid];
    __syncthreads();

    const int tok0 = blockIdx.x * TPBK + warp * TPW;
    const float4* xp = hs4 + (size_t)tok0 * (NH / 4);

    u64 acc[TPW][NE];
#pragma unroll
    for (int t = 0; t < TPW; t++)
#pragma unroll
        for (int e = 0; e < NE; e++) acc[t][e] = 0ULL;

#pragma unroll 2
    for (int i = 0; i < NITER; i++) {
        u64 w[16];
#pragma unroll
        for (int j = 0; j < 16; j++)
            w[j] = shw[((i * 16 + j) << 5) + lane];
#pragma unroll
        for (int t = 0; t < TPW; t++) {
            float4 x = xp[(size_t)t * (NH / 4) + i * 32 + lane];
            u64 x01 = pack2(x.x, x.y);
            u64 x23 = pack2(x.z, x.w);
#pragma unroll
            for (int e = 0; e < NE; e++) {
                fma2(acc[t][e], x01, w[2 * e]);
                fma2(acc[t][e], x23, w[2 * e + 1]);
            }
        }
    }

    // butterfly reduce each (token, expert) accumulator across the warp
#pragma unroll
    for (int off = 16; off; off >>= 1) {
#pragma unroll
        for (int t = 0; t < TPW; t++)
#pragma unroll
            for (int e = 0; e < NE; e++)
                acc[t][e] = add2(acc[t][e],
                                 __shfl_xor_sync(0xffffffffu, acc[t][e], off));
    }
    if (lane == 0) {
#pragma unroll
        for (int t = 0; t < TPW; t++)
#pragma unroll
            for (int e = 0; e < NE; e++)
                sh_logit[(warp * TPW + t) * 9 + e] = fold2(acc[t][e]) + sh_bias[e];
    }
    __syncthreads();

    // per-token softmax stats (first-max argmax matches jnp.argmax)
    if (tid < TPBK) {
        const float* l = sh_logit + tid * 9;
        float best = l[0]; int bi = 0;
#pragma unroll
        for (int e = 1; e < NE; e++) {
            float v = l[e];
            if (v > best) { best = v; bi = e; }
        }
        float s = 0.f;
#pragma unroll
        for (int e = 0; e < NE; e++) s += expf(l[e] - best);
        sh_arg[tid] = bi;
        int gt = blockIdx.x * TPBK + tid;
        out[(size_t)NTOK * NE + gt] = 1.0f / s;      // max prob
        g_expert_id[gt] = (unsigned char)bi;
    }
    __syncthreads();

    // write one-hot (pre-capacity) and logits: thread (t, e)
    {
        int t = tid >> 3, e = tid & 7;
        int gt = blockIdx.x * TPBK + t;
        out[(size_t)gt * NE + e] = (e == sh_arg[t]) ? 1.0f : 0.0f;
        out[(size_t)NTOK * NE + NTOK + (size_t)gt * NE + e] = sh_logit[t * 9 + e];
    }
}

// ---------------------------------------------------------------------------
// Kernel 2: per-group inclusive cumsum of assignments; zero over-capacity
// one-hot entries. 8 blocks x 1024 threads, 2 tokens/thread.
// ---------------------------------------------------------------------------
__global__ void capacity_kernel(float* __restrict__ out) {
    const int g = blockIdx.x;
    const int tid = threadIdx.x;           // 1024
    const int lane = tid & 31, wrp = tid >> 5;

    unsigned short ids =
        ((const unsigned short*)g_expert_id)[g * (NT / 2) + tid];
    int e0 = ids & 0xFF, e1 = ids >> 8;

    int c[NE], s[NE];
#pragma unroll
    for (int e = 0; e < NE; e++) {
        c[e] = (e0 == e) + (e1 == e);
        s[e] = c[e];
    }
#pragma unroll
    for (int off = 1; off < 32; off <<= 1) {
#pragma unroll
        for (int e = 0; e < NE; e++) {
            int v = __shfl_up_sync(0xffffffffu, s[e], off);
            if (lane >= off) s[e] += v;
        }
    }

    __shared__ int wt[32][NE];
    if (lane == 31) {
#pragma unroll
        for (int e = 0; e < NE; e++) wt[wrp][e] = s[e];
    }
    __syncthreads();
    if (tid < NE) {
        int run = 0;
#pragma unroll
        for (int w = 0; w < 32; w++) {
            int v = wt[w][tid];
            wt[w][tid] = run;
            run += v;
        }
    }
    __syncthreads();

    const size_t tok = (size_t)g * NT + (size_t)tid * 2;
#pragma unroll
    for (int e = 0; e < NE; e++) {
        int base = (s[e] - c[e]) + wt[wrp][e];   // exclusive prefix
        if (e == e0 && base + 1 > CAP)
            out[tok * NE + e] = 0.0f;
        int inc0 = (e == e0);
        if (e == e1 && base + inc0 + 1 > CAP)
            out[(tok + 1) * NE + e] = 0.0f;
    }
}

// ---------------------------------------------------------------------------
extern "C" void kernel_launch(void* const* d_in, const int* in_sizes, int n_in,
                              void* d_out, int out_size) {
    const float4* hs = (const float4*)d_in[0];  // [8, 2048, 2048] f32
    const float* W   = (const float*)d_in[1];   // [8, 2048] f32
    const float* b   = (const float*)d_in[2];   // [8] f32
    float* out = (float*)d_out;

    const int smem = NE * NH / 2 * 8            // W u64
                   + TPBK * 9 * 4               // logits
                   + 8 * 4                      // bias
                   + TPBK * 4;                  // argmax
    cudaFuncSetAttribute(router_kernel,
                         cudaFuncAttributeMaxDynamicSharedMemorySize, smem);

    router_kernel<<<NTOK / TPBK, THREADS, smem>>>(hs, W, b, out);
    capacity_kernel<<<NG, NT / 2>>>(out);
}

// round 3
// speedup vs baseline: 1.6121x; 1.0855x over previous
#include <cuda_runtime.h>
#include <math.h>

typedef unsigned long long u64;

#define NG 8
#define NT 2048
#define NH 2048
#define NE 8
#define CAP 320
#define NTOK (NG * NT)        // 16384
#define TPW 4                 // tokens per warp per tile
#define TPT 32                // tokens per tile (8 warps * 4)
#define TILES 2               // tiles per block -> 64 tokens/block
#define TPBK (TPT * TILES)    // 64
#define NBLK (NTOK / TPBK)    // 256
#define BPG (NBLK / NG)       // 32 blocks per group
#define THREADS 256
#define NITER 16              // H chunks of 128 floats

// scratch: argmax expert id per token; per-group completion counters.
// g_cnt is tested modulo BPG, so it never needs resetting across graph replays.
__device__ unsigned char g_expert_id[NTOK];
__device__ unsigned int  g_cnt[NG];

__device__ __forceinline__ void fma2(u64& acc, u64 a, u64 b) {
    asm("fma.rn.f32x2 %0, %1, %2, %0;" : "+l"(acc) : "l"(a), "l"(b));
}
__device__ __forceinline__ u64 add2(u64 a, u64 b) {
    u64 r; asm("add.rn.f32x2 %0, %1, %2;" : "=l"(r) : "l"(a), "l"(b));
    return r;
}
__device__ __forceinline__ u64 pack2(float lo, float hi) {
    u64 r; asm("mov.b64 %0, {%1, %2};" : "=l"(r) : "f"(lo), "f"(hi));
    return r;
}
__device__ __forceinline__ float fold2(u64 v) {
    float a, b; asm("mov.b64 {%0, %1}, %2;" : "=f"(a), "=f"(b) : "l"(v));
    return a + b;
}

// ---------------------------------------------------------------------------
// Capacity epilogue: per-group inclusive cumsum of assignments; zero the
// over-capacity one-hot entries. Executed by the LAST router block of each
// group (256 threads, 8 tokens/thread, 8-warp two-level scan).
// ---------------------------------------------------------------------------
__device__ void capacity_epilogue(int g, float* __restrict__ out) {
    const int tid = threadIdx.x;           // 256
    const int lane = tid & 31, wrp = tid >> 5;

    u64 ids = ((const u64*)g_expert_id)[g * (NT / 8) + tid];

    int c[NE], s[NE];
#pragma unroll
    for (int e = 0; e < NE; e++) c[e] = 0;
#pragma unroll
    for (int i = 0; i < 8; i++) {
        int e = (int)((ids >> (8 * i)) & 0xFFULL);
#pragma unroll
        for (int ee = 0; ee < NE; ee++) c[ee] += (e == ee);
    }
#pragma unroll
    for (int e = 0; e < NE; e++) s[e] = c[e];
#pragma unroll
    for (int off = 1; off < 32; off <<= 1) {
#pragma unroll
        for (int e = 0; e < NE; e++) {
            int v = __shfl_up_sync(0xffffffffu, s[e], off);
            if (lane >= off) s[e] += v;
        }
    }

    __shared__ int wt[8][NE];
    if (lane == 31) {
#pragma unroll
        for (int e = 0; e < NE; e++) wt[wrp][e] = s[e];
    }
    __syncthreads();
    if (tid < NE) {            // exclusive scan of 8 warp totals
        int run = 0;
#pragma unroll
        for (int w = 0; w < 8; w++) {
            int v = wt[w][tid];
            wt[w][tid] = run;
            run += v;
        }
    }
    __syncthreads();

    int base[NE];
#pragma unroll
    for (int e = 0; e < NE; e++) base[e] = (s[e] - c[e]) + wt[wrp][e];

    int run2[NE];
#pragma unroll
    for (int e = 0; e < NE; e++) run2[e] = 0;

    const size_t tok0 = (size_t)g * NT + (size_t)tid * 8;
#pragma unroll
    for (int i = 0; i < 8; i++) {
        int e = (int)((ids >> (8 * i)) & 0xFFULL);
#pragma unroll
        for (int ee = 0; ee < NE; ee++) {
            int inc = (e == ee);
            run2[ee] += inc;
            if (inc && (base[ee] + run2[ee] > CAP))
                out[(tok0 + i) * NE + ee] = 0.0f;
        }
    }
}

// ---------------------------------------------------------------------------
// Router kernel: warp = 4 tokens/tile, lanes span H (coalesced LDG.128).
// Token loads front-batched per iteration for MLP>=4. W in smem,
// lane-transposed u64 pairs -> conflict-free broadcast-free LDS.64.
// Capacity pass fused as last-block-per-group epilogue.
// ---------------------------------------------------------------------------
__global__ __launch_bounds__(THREADS, 2)
void router_kernel(const float4* __restrict__ hs4,
                   const float* __restrict__ W,
                   const float* __restrict__ bias,
                   float* __restrict__ out) {
    extern __shared__ char smem[];
    u64*   shw      = (u64*)smem;                       // 8192 u64 = 64 KB
    float* sh_logit = (float*)(shw + NE * NH / 2);      // 32*9
    float* sh_bias  = sh_logit + TPT * 9;               // 8
    int*   sh_arg   = (int*)(sh_bias + 8);              // 32

    const int tid  = threadIdx.x;
    const int lane = tid & 31, warp = tid >> 5;

    // W permuted: slot[(i*16 + e*2 + d)*32 + l] = (W[e][h], W[e][h+1]),
    // h = 2*(i*64 + 2l + d) -> mainloop LDS.64 at consecutive-lane addresses.
    const float2* W2 = (const float2*)W;
    for (int u = tid; u < NE * NH / 2; u += THREADS) {
        int e = u >> 10, h2 = u & 1023;
        int i = h2 >> 6, r = h2 & 63, l = r >> 1, d = r & 1;
        float2 w = W2[u];
        shw[((i * 16 + e * 2 + d) << 5) + l] = pack2(w.x, w.y);
    }
    if (tid < 8) sh_bias[tid] = bias[tid];
    __syncthreads();

    for (int tile = 0; tile < TILES; tile++) {
        const int tok0 = blockIdx.x * TPBK + tile * TPT + warp * TPW;
        const float4* xp = hs4 + (size_t)tok0 * (NH / 4);

        u64 acc[TPW][NE];
#pragma unroll
        for (int t = 0; t < TPW; t++)
#pragma unroll
            for (int e = 0; e < NE; e++) acc[t][e] = 0ULL;

        for (int i = 0; i < NITER; i++) {
            // front-batched token loads: 4 independent LDG.128
            float4 xv[TPW];
#pragma unroll
            for (int t = 0; t < TPW; t++)
                xv[t] = xp[(size_t)t * (NH / 4) + i * 32 + lane];

            u64 x01[TPW], x23[TPW];
#pragma unroll
            for (int t = 0; t < TPW; t++) {
                x01[t] = pack2(xv[t].x, xv[t].y);
                x23[t] = pack2(xv[t].z, xv[t].w);
            }
#pragma unroll
            for (int e = 0; e < NE; e++) {
                u64 w0 = shw[((i * 16 + 2 * e) << 5) + lane];
                u64 w1 = shw[((i * 16 + 2 * e + 1) << 5) + lane];
#pragma unroll
                for (int t = 0; t < TPW; t++) {
                    fma2(acc[t][e], x01[t], w0);
                    fma2(acc[t][e], x23[t], w1);
                }
            }
        }

        // butterfly-reduce each (token, expert) accumulator across the warp
#pragma unroll
        for (int off = 16; off; off >>= 1) {
#pragma unroll
            for (int t = 0; t < TPW; t++)
#pragma unroll
                for (int e = 0; e < NE; e++)
                    acc[t][e] = add2(acc[t][e],
                                     __shfl_xor_sync(0xffffffffu, acc[t][e], off));
        }
        if (lane == 0) {
#pragma unroll
            for (int t = 0; t < TPW; t++)
#pragma unroll
                for (int e = 0; e < NE; e++)
                    sh_logit[(warp * TPW + t) * 9 + e] =
                        fold2(acc[t][e]) + sh_bias[e];
        }
        __syncthreads();

        // softmax stats + argmax (first-max semantics matches jnp.argmax)
        if (tid < TPT) {
            const float* l = sh_logit + tid * 9;
            float best = l[0]; int bi = 0;
#pragma unroll
            for (int e = 1; e < NE; e++) {
                float v = l[e];
                if (v > best) { best = v; bi = e; }
            }
            float s = 0.f;
#pragma unroll
            for (int e = 0; e < NE; e++) s += expf(l[e] - best);
            sh_arg[tid] = bi;
            int gt = blockIdx.x * TPBK + tile * TPT + tid;
            out[(size_t)NTOK * NE + gt] = 1.0f / s;      // max router prob
            g_expert_id[gt] = (unsigned char)bi;
        }
        __syncthreads();

        // one-hot (pre-capacity) + logits: thread = (token t, expert e)
        {
            int t = tid >> 3, e = tid & 7;
            int gt = blockIdx.x * TPBK + tile * TPT + t;
            out[(size_t)gt * NE + e] = (e == sh_arg[t]) ? 1.0f : 0.0f;
            out[(size_t)NTOK * NE + NTOK + (size_t)gt * NE + e] =
                sh_logit[t * 9 + e];
        }
        __syncthreads();
    }

    // ---- fused capacity epilogue: last block of each group runs it ----
    __threadfence();
    __syncthreads();
    __shared__ int s_last;
    if (tid == 0) {
        unsigned int v = atomicAdd(&g_cnt[blockIdx.x >> 5], 1u);
        s_last = ((v & (BPG - 1)) == (BPG - 1));
    }
    __syncthreads();
    if (s_last) {
        __threadfence();   // acquire side: see all group blocks' writes
        capacity_epilogue(blockIdx.x >> 5, out);
    }
}

// ---------------------------------------------------------------------------
extern "C" void kernel_launch(void* const* d_in, const int* in_sizes, int n_in,
                              void* d_out, int out_size) {
    const float4* hs = (const float4*)d_in[0];  // [8, 2048, 2048] f32
    const float* W   = (const float*)d_in[1];   // [8, 2048] f32
    const float* b   = (const float*)d_in[2];   // [8] f32
    float* out = (float*)d_out;

    const int smem = NE * NH / 2 * 8            // W u64
                   + TPT * 9 * 4                // logits
                   + 8 * 4                      // bias
                   + TPT * 4;                   // argmax
    cudaFuncSetAttribute(router_kernel,
                         cudaFuncAttributeMaxDynamicSharedMemorySize, smem);

    router_kernel<<<NBLK, THREADS, smem>>>(hs, W, b, out);
}

// round 4
// speedup vs baseline: 1.6239x; 1.0073x over previous
#include <cuda_runtime.h>
#include <math.h>

typedef unsigned long long u64;

#define NG 8
#define NT 2048
#define NH 2048
#define NE 8
#define CAP 320
#define NTOK (NG * NT)        // 16384
#define TPW 4                 // tokens per warp per tile
#define TPT 32                // tokens per tile (8 warps * 4)
#define TILES 2               // tiles per block -> 64 tokens/block
#define TPBK (TPT * TILES)    // 64
#define NBLK (NTOK / TPBK)    // 256
#define BPG (NBLK / NG)       // 32 blocks per group
#define THREADS 256
#define NITER 16              // H chunks of 128 floats

// scratch: argmax expert id per token; per-group completion counters.
// g_cnt is tested modulo BPG, so it never needs resetting across graph replays.
__device__ unsigned char g_expert_id[NTOK];
__device__ unsigned int  g_cnt[NG];

__device__ __forceinline__ void fma2(u64& acc, u64 a, u64 b) {
    asm("fma.rn.f32x2 %0, %1, %2, %0;" : "+l"(acc) : "l"(a), "l"(b));
}
__device__ __forceinline__ u64 add2(u64 a, u64 b) {
    u64 r; asm("add.rn.f32x2 %0, %1, %2;" : "=l"(r) : "l"(a), "l"(b));
    return r;
}
__device__ __forceinline__ u64 pack2(float lo, float hi) {
    u64 r; asm("mov.b64 %0, {%1, %2};" : "=l"(r) : "f"(lo), "f"(hi));
    return r;
}
__device__ __forceinline__ float fold2(u64 v) {
    float a, b; asm("mov.b64 {%0, %1}, %2;" : "=f"(a), "=f"(b) : "l"(v));
    return a + b;
}

// ---------------------------------------------------------------------------
// Capacity epilogue: per-group inclusive cumsum of assignments; zero the
// over-capacity one-hot entries. Executed by the LAST router block of each
// group (256 threads, 8 tokens/thread, 8-warp two-level scan).
// ---------------------------------------------------------------------------
__device__ void capacity_epilogue(int g, float* __restrict__ out) {
    const int tid = threadIdx.x;           // 256
    const int lane = tid & 31, wrp = tid >> 5;

    u64 ids = ((const u64*)g_expert_id)[g * (NT / 8) + tid];

    int c[NE], s[NE];
#pragma unroll
    for (int e = 0; e < NE; e++) c[e] = 0;
#pragma unroll
    for (int i = 0; i < 8; i++) {
        int e = (int)((ids >> (8 * i)) & 0xFFULL);
#pragma unroll
        for (int ee = 0; ee < NE; ee++) c[ee] += (e == ee);
    }
#pragma unroll
    for (int e = 0; e < NE; e++) s[e] = c[e];
#pragma unroll
    for (int off = 1; off < 32; off <<= 1) {
#pragma unroll
        for (int e = 0; e < NE; e++) {
            int v = __shfl_up_sync(0xffffffffu, s[e], off);
            if (lane >= off) s[e] += v;
        }
    }

    __shared__ int wt[8][NE];
    if (lane == 31) {
#pragma unroll
        for (int e = 0; e < NE; e++) wt[wrp][e] = s[e];
    }
    __syncthreads();
    if (tid < NE) {            // exclusive scan of 8 warp totals
        int run = 0;
#pragma unroll
        for (int w = 0; w < 8; w++) {
            int v = wt[w][tid];
            wt[w][tid] = run;
            run += v;
        }
    }
    __syncthreads();

    int base[NE];
#pragma unroll
    for (int e = 0; e < NE; e++) base[e] = (s[e] - c[e]) + wt[wrp][e];

    int run2[NE];
#pragma unroll
    for (int e = 0; e < NE; e++) run2[e] = 0;

    const size_t tok0 = (size_t)g * NT + (size_t)tid * 8;
#pragma unroll
    for (int i = 0; i < 8; i++) {
        int e = (int)((ids >> (8 * i)) & 0xFFULL);
#pragma unroll
        for (int ee = 0; ee < NE; ee++) {
            int inc = (e == ee);
            run2[ee] += inc;
            if (inc && (base[ee] + run2[ee] > CAP))
                out[(tok0 + i) * NE + ee] = 0.0f;
        }
    }
}

// ---------------------------------------------------------------------------
// Router kernel: warp = 4 tokens/tile, lanes span H (coalesced LDG.128).
// Token loads front-batched per iteration for MLP>=4. W in smem,
// lane-transposed u64 pairs -> conflict-free broadcast-free LDS.64.
// Capacity pass fused as last-block-per-group epilogue.
// ---------------------------------------------------------------------------
__global__ __launch_bounds__(THREADS, 2)
void router_kernel(const float4* __restrict__ hs4,
                   const float* __restrict__ W,
                   const float* __restrict__ bias,
                   float* __restrict__ out) {
    extern __shared__ char smem[];
    u64*   shw      = (u64*)smem;                       // 8192 u64 = 64 KB
    float* sh_logit = (float*)(shw + NE * NH / 2);      // 32*9
    float* sh_bias  = sh_logit + TPT * 9;               // 8
    int*   sh_arg   = (int*)(sh_bias + 8);              // 32

    const int tid  = threadIdx.x;
    const int lane = tid & 31, warp = tid >> 5;

    // W permuted: slot[(i*16 + e*2 + d)*32 + l] = (W[e][h], W[e][h+1]),
    // h = 2*(i*64 + 2l + d) -> mainloop LDS.64 at consecutive-lane addresses.
    const float2* W2 = (const float2*)W;
    for (int u = tid; u < NE * NH / 2; u += THREADS) {
        int e = u >> 10, h2 = u & 1023;
        int i = h2 >> 6, r = h2 & 63, l = r >> 1, d = r & 1;
        float2 w = W2[u];
        shw[((i * 16 + e * 2 + d) << 5) + l] = pack2(w.x, w.y);
    }
    if (tid < 8) sh_bias[tid] = bias[tid];
    __syncthreads();

    for (int tile = 0; tile < TILES; tile++) {
        const int tok0 = blockIdx.x * TPBK + tile * TPT + warp * TPW;
        const float4* xp = hs4 + (size_t)tok0 * (NH / 4);

        u64 acc[TPW][NE];
#pragma unroll
        for (int t = 0; t < TPW; t++)
#pragma unroll
            for (int e = 0; e < NE; e++) acc[t][e] = 0ULL;

        for (int i = 0; i < NITER; i++) {
            // front-batched token loads: 4 independent LDG.128
            float4 xv[TPW];
#pragma unroll
            for (int t = 0; t < TPW; t++)
                xv[t] = xp[(size_t)t * (NH / 4) + i * 32 + lane];

            u64 x01[TPW], x23[TPW];
#pragma unroll
            for (int t = 0; t < TPW; t++) {
                x01[t] = pack2(xv[t].x, xv[t].y);
                x23[t] = pack2(xv[t].z, xv[t].w);
            }
#pragma unroll
            for (int e = 0; e < NE; e++) {
                u64 w0 = shw[((i * 16 + 2 * e) << 5) + lane];
                u64 w1 = shw[((i * 16 + 2 * e + 1) << 5) + lane];
#pragma unroll
                for (int t = 0; t < TPW; t++) {
                    fma2(acc[t][e], x01[t], w0);
                    fma2(acc[t][e], x23[t], w1);
                }
            }
        }

        // butterfly-reduce each (token, expert) accumulator across the warp
#pragma unroll
        for (int off = 16; off; off >>= 1) {
#pragma unroll
            for (int t = 0; t < TPW; t++)
#pragma unroll
                for (int e = 0; e < NE; e++)
                    acc[t][e] = add2(acc[t][e],
                                     __shfl_xor_sync(0xffffffffu, acc[t][e], off));
        }
        if (lane == 0) {
#pragma unroll
            for (int t = 0; t < TPW; t++)
#pragma unroll
                for (int e = 0; e < NE; e++)
                    sh_logit[(warp * TPW + t) * 9 + e] =
                        fold2(acc[t][e]) + sh_bias[e];
        }
        __syncthreads();

        // softmax stats + argmax (first-max semantics matches jnp.argmax)
        if (tid < TPT) {
            const float* l = sh_logit + tid * 9;
            float best = l[0]; int bi = 0;
#pragma unroll
            for (int e = 1; e < NE; e++) {
                float v = l[e];
                if (v > best) { best = v; bi = e; }
            }
            float s = 0.f;
#pragma unroll
            for (int e = 0; e < NE; e++) s += expf(l[e] - best);
            sh_arg[tid] = bi;
            int gt = blockIdx.x * TPBK + tile * TPT + tid;
            out[(size_t)NTOK * NE + gt] = 1.0f / s;      // max router prob
            g_expert_id[gt] = (unsigned char)bi;
        }
        __syncthreads();

        // one-hot (pre-capacity) + logits: thread = (token t, expert e)
        {
            int t = tid >> 3, e = tid & 7;
            int gt = blockIdx.x * TPBK + tile * TPT + t;
            out[(size_t)gt * NE + e] = (e == sh_arg[t]) ? 1.0f : 0.0f;
            out[(size_t)NTOK * NE + NTOK + (size_t)gt * NE + e] =
                sh_logit[t * 9 + e];
        }
        __syncthreads();
    }

    // ---- fused capacity epilogue: last block of each group runs it ----
    __threadfence();
    __syncthreads();
    __shared__ int s_last;
    if (tid == 0) {
        unsigned int v = atomicAdd(&g_cnt[blockIdx.x >> 5], 1u);
        s_last = ((v & (BPG - 1)) == (BPG - 1));
    }
    __syncthreads();
    if (s_last) {
        __threadfence();   // acquire side: see all group blocks' writes
        capacity_epilogue(blockIdx.x >> 5, out);
    }
}

// ---------------------------------------------------------------------------
extern "C" void kernel_launch(void* const* d_in, const int* in_sizes, int n_in,
                              void* d_out, int out_size) {
    const float4* hs = (const float4*)d_in[0];  // [8, 2048, 2048] f32
    const float* W   = (const float*)d_in[1];   // [8, 2048] f32
    const float* b   = (const float*)d_in[2];   // [8] f32
    float* out = (float*)d_out;

    const int smem = NE * NH / 2 * 8            // W u64
                   + TPT * 9 * 4                // logits
                   + 8 * 4                      // bias
                   + TPT * 4;                   // argmax
    cudaFuncSetAttribute(router_kernel,
                         cudaFuncAttributeMaxDynamicSharedMemorySize, smem);

    router_kernel<<<NBLK, THREADS, smem>>>(hs, W, b, out);
}

// round 5
// speedup vs baseline: 1.7322x; 1.0667x over previous
#include <cuda_runtime.h>
#include <math.h>

typedef unsigned long long u64;

#define NG 8
#define NT 2048
#define NH 2048
#define NE 8
#define CAP 320
#define NTOK (NG * NT)        // 16384
#define TPW 4                 // tokens per warp per tile
#define TPT 32                // tokens per tile (8 warps * 4)
#define TILES 2               // tiles per block -> 64 tokens/block
#define TPBK (TPT * TILES)    // 64
#define NBLK (NTOK / TPBK)    // 256 (single wave: 2 CTA/SM * 148 = 296)
#define BPG (NBLK / NG)       // 32 blocks per group
#define THREADS 256
#define NITER 16              // H chunks of 128 floats

// scratch: argmax expert id per token; per-group completion counters.
// g_cnt is tested modulo BPG, so it never needs resetting across graph replays.
__device__ unsigned char g_expert_id[NTOK];
__device__ unsigned int  g_cnt[NG];

__device__ __forceinline__ void fma2(u64& acc, u64 a, u64 b) {
    asm("fma.rn.f32x2 %0, %1, %2, %0;" : "+l"(acc) : "l"(a), "l"(b));
}
__device__ __forceinline__ u64 add2(u64 a, u64 b) {
    u64 r; asm("add.rn.f32x2 %0, %1, %2;" : "=l"(r) : "l"(a), "l"(b));
    return r;
}
__device__ __forceinline__ u64 pack2(float lo, float hi) {
    u64 r; asm("mov.b64 %0, {%1, %2};" : "=l"(r) : "f"(lo), "f"(hi));
    return r;
}
__device__ __forceinline__ u64 dup2(float v) { return pack2(v, v); }
__device__ __forceinline__ void unpack2(u64 v, float& lo, float& hi) {
    asm("mov.b64 {%0, %1}, %2;" : "=f"(lo), "=f"(hi) : "l"(v));
}

// ---------------------------------------------------------------------------
// Capacity epilogue: per-group inclusive cumsum of assignments; zero the
// over-capacity one-hot entries. Executed by the LAST router block per group.
// ---------------------------------------------------------------------------
__device__ void capacity_epilogue(int g, float* __restrict__ out) {
    const int tid = threadIdx.x;           // 256
    const int lane = tid & 31, wrp = tid >> 5;

    u64 ids = ((const u64*)g_expert_id)[g * (NT / 8) + tid];

    int c[NE], s[NE];
#pragma unroll
    for (int e = 0; e < NE; e++) c[e] = 0;
#pragma unroll
    for (int i = 0; i < 8; i++) {
        int e = (int)((ids >> (8 * i)) & 0xFFULL);
#pragma unroll
        for (int ee = 0; ee < NE; ee++) c[ee] += (e == ee);
    }
#pragma unroll
    for (int e = 0; e < NE; e++) s[e] = c[e];
#pragma unroll
    for (int off = 1; off < 32; off <<= 1) {
#pragma unroll
        for (int e = 0; e < NE; e++) {
            int v = __shfl_up_sync(0xffffffffu, s[e], off);
            if (lane >= off) s[e] += v;
        }
    }

    __shared__ int wt[8][NE];
    if (lane == 31) {
#pragma unroll
        for (int e = 0; e < NE; e++) wt[wrp][e] = s[e];
    }
    __syncthreads();
    if (tid < NE) {            // exclusive scan of 8 warp totals
        int run = 0;
#pragma unroll
        for (int w = 0; w < 8; w++) {
            int v = wt[w][tid];
            wt[w][tid] = run;
            run += v;
        }
    }
    __syncthreads();

    int base[NE];
#pragma unroll
    for (int e = 0; e < NE; e++) base[e] = (s[e] - c[e]) + wt[wrp][e];

    int run2[NE];
#pragma unroll
    for (int e = 0; e < NE; e++) run2[e] = 0;

    const size_t tok0 = (size_t)g * NT + (size_t)tid * 8;
#pragma unroll
    for (int i = 0; i < 8; i++) {
        int e = (int)((ids >> (8 * i)) & 0xFFULL);
#pragma unroll
        for (int ee = 0; ee < NE; ee++) {
            int inc = (e == ee);
            run2[ee] += inc;
            if (inc && (base[ee] + run2[ee] > CAP))
                out[(tok0 + i) * NE + ee] = 0.0f;
        }
    }
}

// ---------------------------------------------------------------------------
// Router kernel. warp = 4 tokens, lanes span H (coalesced LDG.128).
// Expert-PAIR packed FFMA2: acc[t][p] holds (logit[2p], logit[2p+1]),
// operand a = (x,x), b = (W[2p][h], W[2p+1][h])  -> 32 acc regs/thread.
// 2-deep register double-buffer keeps 8 LDG.128/warp outstanding.
// ---------------------------------------------------------------------------
__global__ __launch_bounds__(THREADS, 2)
void router_kernel(const float4* __restrict__ hs4,
                   const float* __restrict__ W,
                   const float* __restrict__ bias,
                   float* __restrict__ out) {
    extern __shared__ char smem[];
    u64*   shw      = (u64*)smem;                       // 8192 u64 = 64 KB
    float* sh_logit = (float*)(shw + NE * NH / 2);      // 32*9
    float* sh_bias  = sh_logit + TPT * 9;               // 8
    int*   sh_arg   = (int*)(sh_bias + 8);              // 32

    const int tid  = threadIdx.x;
    const int lane = tid & 31, warp = tid >> 5;

    // W permuted for expert-pair packing:
    // word[(i*16 + j*4 + p)*32 + l] = (W[2p][h], W[2p+1][h]),
    //   h = i*128 + l*4 + j  (i = H chunk, l = lane, j = 0..3 within float4)
    // -> mainloop LDS.64 at consecutive-lane addresses (conflict-free).
    {
        const float2* W2 = (const float2*)W;
        float* shwf = (float*)shw;
        for (int u = tid; u < NE * NH / 2; u += THREADS) {
            int e = u >> 10;
            int h = (u & 1023) * 2;           // even h; pair (h, h+1)
            float2 w = W2[u];
            int i = h >> 7, l = (h >> 2) & 31, j = h & 3;
            int p = e >> 1, pos = e & 1;
            int w0 = ((i * 16 + j * 4 + p) << 5) + l;
            int w1 = ((i * 16 + (j + 1) * 4 + p) << 5) + l;
            shwf[w0 * 2 + pos] = w.x;
            shwf[w1 * 2 + pos] = w.y;
        }
    }
    if (tid < 8) sh_bias[tid] = bias[tid];
    __syncthreads();

    for (int tile = 0; tile < TILES; tile++) {
        const int tok0 = blockIdx.x * TPBK + tile * TPT + warp * TPW;
        const float4* xp = hs4 + (size_t)tok0 * (NH / 4) + lane;

        u64 acc[TPW][4];
#pragma unroll
        for (int t = 0; t < TPW; t++)
#pragma unroll
            for (int p = 0; p < 4; p++) acc[t][p] = 0ULL;

        // prime 2-deep pipeline
        float4 buf0[TPW], buf1[TPW];
#pragma unroll
        for (int t = 0; t < TPW; t++) buf0[t] = xp[t * (NH / 4)];
#pragma unroll
        for (int t = 0; t < TPW; t++) buf1[t] = xp[t * (NH / 4) + 32];

#pragma unroll
        for (int i = 0; i < NITER; i++) {
            // grab current buffer into cur, immediately refill it for i+2
            float4 cur[TPW];
#pragma unroll
            for (int t = 0; t < TPW; t++)
                cur[t] = (i & 1) ? buf1[t] : buf0[t];
            if (i + 2 < NITER) {
#pragma unroll
                for (int t = 0; t < TPW; t++) {
                    float4 v = xp[t * (NH / 4) + (i + 2) * 32];
                    if (i & 1) buf1[t] = v; else buf0[t] = v;
                }
            }

            u64 w[16];
#pragma unroll
            for (int q = 0; q < 16; q++)
                w[q] = shw[(((i << 4) + q) << 5) + lane];

#pragma unroll
            for (int t = 0; t < TPW; t++) {
                u64 x0 = dup2(cur[t].x), x1 = dup2(cur[t].y);
                u64 x2 = dup2(cur[t].z), x3 = dup2(cur[t].w);
#pragma unroll
                for (int p = 0; p < 4; p++) {
                    fma2(acc[t][p], x0, w[0 * 4 + p]);
                    fma2(acc[t][p], x1, w[1 * 4 + p]);
                    fma2(acc[t][p], x2, w[2 * 4 + p]);
                    fma2(acc[t][p], x3, w[3 * 4 + p]);
                }
            }
        }

        // butterfly-reduce packed (token, expert-pair) accumulators
#pragma unroll
        for (int off = 16; off; off >>= 1) {
#pragma unroll
            for (int t = 0; t < TPW; t++)
#pragma unroll
                for (int p = 0; p < 4; p++)
                    acc[t][p] = add2(acc[t][p],
                                     __shfl_xor_sync(0xffffffffu, acc[t][p], off));
        }
        if (lane == 0) {
#pragma unroll
            for (int t = 0; t < TPW; t++)
#pragma unroll
                for (int p = 0; p < 4; p++) {
                    float lo, hi;
                    unpack2(acc[t][p], lo, hi);
                    sh_logit[(warp * TPW + t) * 9 + 2 * p]     = lo + sh_bias[2 * p];
                    sh_logit[(warp * TPW + t) * 9 + 2 * p + 1] = hi + sh_bias[2 * p + 1];
                }
        }
        __syncthreads();

        // softmax stats + argmax (first-max semantics matches jnp.argmax)
        if (tid < TPT) {
            const float* l = sh_logit + tid * 9;
            float best = l[0]; int bi = 0;
#pragma unroll
            for (int e = 1; e < NE; e++) {
                float v = l[e];
                if (v > best) { best = v; bi = e; }
            }
            float s = 0.f;
#pragma unroll
            for (int e = 0; e < NE; e++) s += expf(l[e] - best);
            sh_arg[tid] = bi;
            int gt = blockIdx.x * TPBK + tile * TPT + tid;
            out[(size_t)NTOK * NE + gt] = 1.0f / s;      // max router prob
            g_expert_id[gt] = (unsigned char)bi;
        }
        __syncthreads();

        // one-hot (pre-capacity) + logits: thread = (token t, expert e)
        {
            int t = tid >> 3, e = tid & 7;
            int gt = blockIdx.x * TPBK + tile * TPT + t;
            out[(size_t)gt * NE + e] = (e == sh_arg[t]) ? 1.0f : 0.0f;
            out[(size_t)NTOK * NE + NTOK + (size_t)gt * NE + e] =
                sh_logit[t * 9 + e];
        }
        __syncthreads();
    }

    // ---- fused capacity epilogue: last block of each group runs it ----
    __threadfence();
    __syncthreads();
    __shared__ int s_last;
    if (tid == 0) {
        unsigned int v = atomicAdd(&g_cnt[blockIdx.x >> 5], 1u);
        s_last = ((v & (BPG - 1)) == (BPG - 1));
    }
    __syncthreads();
    if (s_last) {
        __threadfence();   // acquire: see all group blocks' writes
        capacity_epilogue(blockIdx.x >> 5, out);
    }
}

// ---------------------------------------------------------------------------
extern "C" void kernel_launch(void* const* d_in, const int* in_sizes, int n_in,
                              void* d_out, int out_size) {
    const float4* hs = (const float4*)d_in[0];  // [8, 2048, 2048] f32
    const float* W   = (const float*)d_in[1];   // [8, 2048] f32
    const float* b   = (const float*)d_in[2];   // [8] f32
    float* out = (float*)d_out;

    const int smem = NE * NH / 2 * 8            // W u64 (pair-packed)
                   + TPT * 9 * 4                // logits
                   + 8 * 4                      // bias
                   + TPT * 4;                   // argmax
    cudaFuncSetAttribute(router_kernel,
                         cudaFuncAttributeMaxDynamicSharedMemorySize, smem);

    router_kernel<<<NBLK, THREADS, smem>>>(hs, W, b, out);
}